// round 3
// baseline (speedup 1.0000x reference)
#include <cuda_runtime.h>
#include <cuda_bf16.h>
#include <math.h>
#include <stdint.h>

#define NN   8192
#define DIN  512
#define DHID 256
#define DOUT 128
#define CAP  256
#define NEG  0.25f

// ---------------- scratch (device globals) ----------------------------------
__device__ float g_y1[NN * DHID];
__device__ float g_y2[NN * DHID];
__device__ float g_h [NN * DOUT];
__device__ float g_f1[NN];
__device__ float g_f2[NN];
__device__ int   g_cnt [NN];
__device__ int   g_ecol[NN * CAP];
__device__ float g_eval[NN * CAP];
__device__ float g_part[64 * DOUT];
__device__ float g_hmean[DOUT];

__device__ __nv_bfloat16 g_xh [NN * DIN],  g_xl [NN * DIN];
__device__ __nv_bfloat16 g_x1h[NN * DHID], g_x1l[NN * DHID];
__device__ __nv_bfloat16 g_x2h[NN * DHID], g_x2l[NN * DHID];
__device__ __nv_bfloat16 g_w1th[DHID * DIN],  g_w1tl[DHID * DIN];
__device__ __nv_bfloat16 g_w2th[DHID * DHID], g_w2tl[DHID * DHID];
__device__ __nv_bfloat16 g_wgth[DOUT * DHID], g_wgtl[DOUT * DHID];

__device__ __forceinline__ float leaky(float x) { return x >= 0.f ? x : NEG * x; }

__device__ __forceinline__ uint32_t smem_to_u32(const void* p) {
    uint32_t a;
    asm("{ .reg .u64 t; cvta.to.shared.u64 t, %1; cvt.u32.u64 %0, t; }" : "=r"(a) : "l"(p));
    return a;
}
__device__ __forceinline__ void ldsm_x4(uint32_t* r, uint32_t addr) {
    asm volatile("ldmatrix.sync.aligned.m8n8.x4.shared.b16 {%0,%1,%2,%3}, [%4];"
                 : "=r"(r[0]), "=r"(r[1]), "=r"(r[2]), "=r"(r[3]) : "r"(addr));
}
__device__ __forceinline__ void mma16816(float* c, const uint32_t* a, uint32_t b0, uint32_t b1) {
    asm volatile("mma.sync.aligned.m16n8k16.row.col.f32.bf16.bf16.f32 "
                 "{%0,%1,%2,%3}, {%4,%5,%6,%7}, {%8,%9}, {%0,%1,%2,%3};"
                 : "+f"(c[0]), "+f"(c[1]), "+f"(c[2]), "+f"(c[3])
                 : "r"(a[0]), "r"(a[1]), "r"(a[2]), "r"(a[3]), "r"(b0), "r"(b1));
}

// ---------------- 1) edge extraction -----------------------------------------
__global__ void k_extract(const float* __restrict__ adj) {
    __shared__ float srow[NN];
    __shared__ int   scnt[256];
    const int row = blockIdx.x, tid = threadIdx.x;
    const float4* arow4 = (const float4*)(adj + (size_t)row * NN);
    float4* srow4 = (float4*)srow;
    for (int j = tid; j < NN / 4; j += 256) srow4[j] = arow4[j];
    __syncthreads();

    int c = 0;
#pragma unroll
    for (int i = 0; i < 32; i++) if (srow[i * 256 + tid] > 0.f) c++;
    scnt[tid] = c;
    __syncthreads();
    for (int off = 1; off < 256; off <<= 1) {
        int v = scnt[tid];
        if (tid >= off) v += scnt[tid - off];
        __syncthreads();
        scnt[tid] = v;
        __syncthreads();
    }
    const int my_off = scnt[tid] - c;
    if (tid == 0) {
        int total = scnt[255];
        g_cnt[row] = total < CAP ? total : CAP;
    }
    const int base = row * CAP;
    int k = 0;
#pragma unroll
    for (int i = 0; i < 32; i++) {
        float v = srow[i * 256 + tid];
        if (v > 0.f) {
            int p = my_off + k;
            if (p < CAP) { g_ecol[base + p] = i * 256 + tid; g_eval[base + p] = v; }
            k++;
        }
    }
}

// ---------------- 2) fp32 -> bf16 hi/lo split ---------------------------------
__global__ void k_split(const float* __restrict__ s, __nv_bfloat16* __restrict__ h,
                        __nv_bfloat16* __restrict__ l, int n) {
    int i = blockIdx.x * 256 + threadIdx.x;
    if (i >= n) return;
    float v = s[i];
    __nv_bfloat16 hb = __float2bfloat16(v);
    h[i] = hb;
    l[i] = __float2bfloat16(v - __bfloat162float(hb));
}

// transpose + split: Wt[n*K + k] = W[k*N + n]
__global__ void k_wt(const float* __restrict__ W, __nv_bfloat16* __restrict__ th,
                     __nv_bfloat16* __restrict__ tl, int K, int N) {
    int idx = blockIdx.x * 256 + threadIdx.x;
    if (idx >= K * N) return;
    int n = idx / K, k = idx - n * K;
    float v = W[(size_t)k * N + n];
    __nv_bfloat16 hb = __float2bfloat16(v);
    th[idx] = hb;
    tl[idx] = __float2bfloat16(v - __bfloat162float(hb));
}

// ---------------- 3) HMMA bf16-split GEMM ------------------------------------
// C[M,N] = (Ah+Al) @ (Bh+Bl)^T, Bt stored [N][K] K-major.
// 512 thr (16 warps), CTA tile 128x128, warp tile 32x32, BK=32.
#define SPAD 40   // smem row stride in halfs (80B: 16B-aligned, conflict-free)
__global__ void __launch_bounds__(512) k_hmma(
    const __nv_bfloat16* __restrict__ Ah, const __nv_bfloat16* __restrict__ Al,
    const __nv_bfloat16* __restrict__ Bh, const __nv_bfloat16* __restrict__ Bl,
    float* __restrict__ C, int N, int K)
{
    __shared__ __nv_bfloat16 sA[2][128 * SPAD];
    __shared__ __nv_bfloat16 sB[2][128 * SPAD];
    const int tid = threadIdx.x, wid = tid >> 5, lane = tid & 31;
    const int m0 = blockIdx.x * 128, n0 = blockIdx.y * 128;
    const int wm = (wid & 3) * 32, wn = (wid >> 2) * 32;

    float acc[2][4][4];
#pragma unroll
    for (int i = 0; i < 2; i++)
#pragma unroll
        for (int j = 0; j < 4; j++)
#pragma unroll
            for (int q = 0; q < 4; q++) acc[i][j][q] = 0.f;

    const uint32_t bA0 = smem_to_u32(sA[0]), bA1 = smem_to_u32(sA[1]);
    const uint32_t bB0 = smem_to_u32(sB[0]), bB1 = smem_to_u32(sB[1]);

    const int row = tid >> 2, ch = tid & 3;          // 128 rows x 4 chunks of 8 halfs
    const int soff = row * SPAD + ch * 8;

    const int nch = K >> 5;
    for (int kc = 0; kc < nch; kc++) {
        const size_t gA = (size_t)(m0 + row) * K + kc * 32 + ch * 8;
        const size_t gB = (size_t)(n0 + row) * K + kc * 32 + ch * 8;
        uint4 vah = *(const uint4*)(Ah + gA);
        uint4 val = *(const uint4*)(Al + gA);
        uint4 vbh = *(const uint4*)(Bh + gB);
        uint4 vbl = *(const uint4*)(Bl + gB);
        __syncthreads();                 // prior iter's reads done
        *(uint4*)&sA[0][soff] = vah;
        *(uint4*)&sA[1][soff] = val;
        *(uint4*)&sB[0][soff] = vbh;
        *(uint4*)&sB[1][soff] = vbl;
        __syncthreads();

#pragma unroll
        for (int ks = 0; ks < 2; ks++) {
            const int kb = ks * 16;
            // A frags: rows wm+16i+(lane&15), col kb+8*(lane>>4)
            const uint32_t aoff = ((wm + (lane & 15)) * SPAD + kb + 8 * (lane >> 4)) * 2;
            uint32_t afr[2][2][4];
            ldsm_x4(afr[0][0], bA0 + aoff);
            ldsm_x4(afr[0][1], bA1 + aoff);
            ldsm_x4(afr[1][0], bA0 + aoff + 16 * SPAD * 2);
            ldsm_x4(afr[1][1], bA1 + aoff + 16 * SPAD * 2);
            // B frags (pairs of n-tiles): rows wn+16p+8*(lane>>4)+(lane&7), col kb+8*((lane>>3)&1)
            const uint32_t boff = ((wn + 8 * (lane >> 4) + (lane & 7)) * SPAD
                                   + kb + 8 * ((lane >> 3) & 1)) * 2;
            uint32_t bfr[2][2][4];
            ldsm_x4(bfr[0][0], bB0 + boff);
            ldsm_x4(bfr[0][1], bB1 + boff);
            ldsm_x4(bfr[1][0], bB0 + boff + 16 * SPAD * 2);
            ldsm_x4(bfr[1][1], bB1 + boff + 16 * SPAD * 2);

#pragma unroll
            for (int i = 0; i < 2; i++)
#pragma unroll
                for (int j = 0; j < 4; j++) {
                    const int p = j >> 1, s = (j & 1) * 2;
                    mma16816(acc[i][j], afr[i][0], bfr[p][0][s], bfr[p][0][s + 1]); // hh
                    mma16816(acc[i][j], afr[i][0], bfr[p][1][s], bfr[p][1][s + 1]); // hl
                    mma16816(acc[i][j], afr[i][1], bfr[p][0][s], bfr[p][0][s + 1]); // lh
                }
        }
    }

    // epilogue
    const int g = lane >> 2, t2 = (lane & 3) * 2;
#pragma unroll
    for (int i = 0; i < 2; i++)
#pragma unroll
        for (int j = 0; j < 4; j++) {
            const int rm = m0 + wm + 16 * i + g;
            const int cn = n0 + wn + 8 * j + t2;
            *(float2*)&C[(size_t)rm * N + cn]       = make_float2(acc[i][j][0], acc[i][j][1]);
            *(float2*)&C[(size_t)(rm + 8) * N + cn] = make_float2(acc[i][j][2], acc[i][j][3]);
        }
}

// ---------------- 4) sparse SpMM + bias + leaky -> bf16 hi/lo -----------------
__global__ void k_spmm(const float* __restrict__ y, const float* __restrict__ bias,
                       __nv_bfloat16* __restrict__ oh, __nv_bfloat16* __restrict__ ol) {
    __shared__ int   scol[CAP];
    __shared__ float sval[CAP];
    const int row = blockIdx.x, tid = threadIdx.x;   // 256 threads
    const int cnt = g_cnt[row];
    for (int t = tid; t < cnt; t += 256) {
        scol[t] = g_ecol[row * CAP + t];
        sval[t] = g_eval[row * CAP + t];
    }
    __syncthreads();
    float acc = 0.f;
    for (int t = 0; t < cnt; t++)
        acc = fmaf(sval[t], y[(size_t)scol[t] * DHID + tid], acc);
    float v = leaky(acc + bias[tid]);
    __nv_bfloat16 hb = __float2bfloat16(v);
    size_t idx = (size_t)row * DHID + tid;
    oh[idx] = hb;
    ol[idx] = __float2bfloat16(v - __bfloat162float(hb));
}

// ---------------- 5) f1 = h@a1, f2 = h@a2 ------------------------------------
__global__ void k_f12(const float* __restrict__ h, const float* __restrict__ a) {
    const int warp = (blockIdx.x * blockDim.x + threadIdx.x) >> 5;
    const int lane = threadIdx.x & 31;
    if (warp >= NN) return;
    const float* hr = h + (size_t)warp * DOUT;
    float s1 = 0.f, s2 = 0.f;
#pragma unroll
    for (int q = 0; q < 4; q++) {
        int c = lane + q * 32;
        float hv = hr[c];
        s1 = fmaf(hv, a[c], s1);
        s2 = fmaf(hv, a[DOUT + c], s2);
    }
#pragma unroll
    for (int o = 16; o; o >>= 1) {
        s1 += __shfl_down_sync(0xffffffffu, s1, o);
        s2 += __shfl_down_sync(0xffffffffu, s2, o);
    }
    if (lane == 0) { g_f1[warp] = s1; g_f2[warp] = s2; }
}

// ---------------- 6) column mean of h ----------------------------------------
__global__ void k_part(const float* __restrict__ h) {
    const int b = blockIdx.x, c = threadIdx.x;
    float s = 0.f;
    for (int r = 0; r < 128; r++) s += h[(size_t)(b * 128 + r) * DOUT + c];
    g_part[b * DOUT + c] = s;
}
__global__ void k_mean() {
    const int c = threadIdx.x;
    float s = 0.f;
    for (int b = 0; b < 64; b++) s += g_part[b * DOUT + c];
    g_hmean[c] = s * (1.f / NN);
}

// ---------------- 7) sparse masked softmax + h_prime + leaky + split ----------
__global__ void k_attn(const float* __restrict__ h, float* __restrict__ out) {
    __shared__ float se[CAP];
    __shared__ int   scol[CAP];
    __shared__ float sred[128];
    const int row = blockIdx.x, tid = threadIdx.x;   // 128 threads
    const int cnt = g_cnt[row];

    if (cnt == 0) {
        float v = leaky(g_hmean[tid]);
        if (tid < 64) out[(size_t)row * 64 + tid] = v;
        else          out[(size_t)NN * 64 + (size_t)row * 64 + (tid - 64)] = v;
        return;
    }

    const float f1i = g_f1[row];
    float lmax = -INFINITY;
    for (int t = tid; t < cnt; t += 128) {
        int j = g_ecol[row * CAP + t];
        float e = leaky(f1i + g_f2[j]);
        scol[t] = j;
        se[t] = e;
        lmax = fmaxf(lmax, e);
    }
    sred[tid] = lmax;
    __syncthreads();
    for (int s = 64; s; s >>= 1) {
        if (tid < s) sred[tid] = fmaxf(sred[tid], sred[tid + s]);
        __syncthreads();
    }
    const float m = sred[0];
    __syncthreads();

    float lsum = 0.f;
    for (int t = tid; t < cnt; t += 128) {
        float w = __expf(se[t] - m);
        se[t] = w;
        lsum += w;
    }
    sred[tid] = lsum;
    __syncthreads();
    for (int s = 64; s; s >>= 1) {
        if (tid < s) sred[tid] += sred[tid + s];
        __syncthreads();
    }
    const float invZ = 1.f / sred[0];

    float acc = 0.f;
    for (int t = 0; t < cnt; t++)
        acc = fmaf(se[t], h[(size_t)scol[t] * DOUT + tid], acc);
    float v = leaky(acc * invZ);
    if (tid < 64) out[(size_t)row * 64 + tid] = v;
    else          out[(size_t)NN * 64 + (size_t)row * 64 + (tid - 64)] = v;
}

// ---------------- launch -----------------------------------------------------
extern "C" void kernel_launch(void* const* d_in, const int* in_sizes, int n_in,
                              void* d_out, int out_size) {
    (void)in_sizes; (void)n_in; (void)out_size;
    const float* x   = (const float*)d_in[0];
    const float* adj = (const float*)d_in[1];
    const float* W1  = (const float*)d_in[2];
    const float* b1  = (const float*)d_in[3];
    const float* W2  = (const float*)d_in[4];
    const float* b2  = (const float*)d_in[5];
    const float* Wg  = (const float*)d_in[6];
    const float* a   = (const float*)d_in[7];
    float* out = (float*)d_out;

    void* p;
    cudaGetSymbolAddress(&p, g_y1);   float* y1 = (float*)p;
    cudaGetSymbolAddress(&p, g_y2);   float* y2 = (float*)p;
    cudaGetSymbolAddress(&p, g_h);    float* h  = (float*)p;
    cudaGetSymbolAddress(&p, g_xh);   __nv_bfloat16* xh  = (__nv_bfloat16*)p;
    cudaGetSymbolAddress(&p, g_xl);   __nv_bfloat16* xl  = (__nv_bfloat16*)p;
    cudaGetSymbolAddress(&p, g_x1h);  __nv_bfloat16* x1h = (__nv_bfloat16*)p;
    cudaGetSymbolAddress(&p, g_x1l);  __nv_bfloat16* x1l = (__nv_bfloat16*)p;
    cudaGetSymbolAddress(&p, g_x2h);  __nv_bfloat16* x2h = (__nv_bfloat16*)p;
    cudaGetSymbolAddress(&p, g_x2l);  __nv_bfloat16* x2l = (__nv_bfloat16*)p;
    cudaGetSymbolAddress(&p, g_w1th); __nv_bfloat16* w1th = (__nv_bfloat16*)p;
    cudaGetSymbolAddress(&p, g_w1tl); __nv_bfloat16* w1tl = (__nv_bfloat16*)p;
    cudaGetSymbolAddress(&p, g_w2th); __nv_bfloat16* w2th = (__nv_bfloat16*)p;
    cudaGetSymbolAddress(&p, g_w2tl); __nv_bfloat16* w2tl = (__nv_bfloat16*)p;
    cudaGetSymbolAddress(&p, g_wgth); __nv_bfloat16* wgth = (__nv_bfloat16*)p;
    cudaGetSymbolAddress(&p, g_wgtl); __nv_bfloat16* wgtl = (__nv_bfloat16*)p;

    k_extract<<<NN, 256>>>(adj);
    k_split<<<(NN * DIN + 255) / 256, 256>>>(x, xh, xl, NN * DIN);
    k_wt<<<(DIN * DHID + 255) / 256, 256>>>(W1, w1th, w1tl, DIN, DHID);
    k_wt<<<(DHID * DHID + 255) / 256, 256>>>(W2, w2th, w2tl, DHID, DHID);
    k_wt<<<(DHID * DOUT + 255) / 256, 256>>>(Wg, wgth, wgtl, DHID, DOUT);

    k_hmma<<<dim3(NN / 128, DHID / 128), 512>>>(xh,  xl,  w1th, w1tl, y1, DHID, DIN);
    k_spmm<<<NN, 256>>>(y1, b1, x1h, x1l);
    k_hmma<<<dim3(NN / 128, DHID / 128), 512>>>(x1h, x1l, w2th, w2tl, y2, DHID, DHID);
    k_spmm<<<NN, 256>>>(y2, b2, x2h, x2l);
    k_hmma<<<dim3(NN / 128, DOUT / 128), 512>>>(x2h, x2l, wgth, wgtl, h,  DOUT, DHID);

    k_f12 <<<NN / 8, 256>>>(h, a);
    k_part<<<64, 128>>>(h);
    k_mean<<<1, 128>>>();
    k_attn<<<NN, 128>>>(h, out);
}

// round 5
// speedup vs baseline: 1.3593x; 1.3593x over previous
#include <cuda_runtime.h>
#include <cuda_bf16.h>
#include <math.h>
#include <stdint.h>

#define NN   8192
#define DIN  512
#define DHID 256
#define DOUT 128
#define CAP  256
#define NEG  0.25f

// ---------------- scratch (device globals) ----------------------------------
__device__ float g_y1[NN * DHID];
__device__ float g_y2[NN * DHID];
__device__ float g_h [NN * DOUT];
__device__ float g_f1[NN];
__device__ float g_f2[NN];
__device__ int   g_cnt [NN];
__device__ int   g_ecol[NN * CAP];
__device__ float g_eval[NN * CAP];
__device__ float g_part[64 * DOUT];
__device__ float g_hmean[DOUT];

__device__ __nv_bfloat16 g_xh [NN * DIN],  g_xl [NN * DIN];
__device__ __nv_bfloat16 g_x1h[NN * DHID], g_x1l[NN * DHID];
__device__ __nv_bfloat16 g_x2h[NN * DHID], g_x2l[NN * DHID];
__device__ __nv_bfloat16 g_w1th[DHID * DIN],  g_w1tl[DHID * DIN];
__device__ __nv_bfloat16 g_w2th[DHID * DHID], g_w2tl[DHID * DHID];
__device__ __nv_bfloat16 g_wgth[DOUT * DHID], g_wgtl[DOUT * DHID];

__device__ __forceinline__ float leaky(float x) { return x >= 0.f ? x : NEG * x; }

__device__ __forceinline__ uint32_t smem_to_u32(const void* p) {
    uint32_t a;
    asm("{ .reg .u64 t; cvta.to.shared.u64 t, %1; cvt.u32.u64 %0, t; }" : "=r"(a) : "l"(p));
    return a;
}
__device__ __forceinline__ void ldsm_x4(uint32_t* r, uint32_t addr) {
    asm volatile("ldmatrix.sync.aligned.m8n8.x4.shared.b16 {%0,%1,%2,%3}, [%4];"
                 : "=r"(r[0]), "=r"(r[1]), "=r"(r[2]), "=r"(r[3]) : "r"(addr));
}
__device__ __forceinline__ void mma16816(float* c, const uint32_t* a, uint32_t b0, uint32_t b1) {
    asm volatile("mma.sync.aligned.m16n8k16.row.col.f32.bf16.bf16.f32 "
                 "{%0,%1,%2,%3}, {%4,%5,%6,%7}, {%8,%9}, {%0,%1,%2,%3};"
                 : "+f"(c[0]), "+f"(c[1]), "+f"(c[2]), "+f"(c[3])
                 : "r"(a[0]), "r"(a[1]), "r"(a[2]), "r"(a[3]), "r"(b0), "r"(b1));
}
__device__ __forceinline__ void cp16(uint32_t saddr, const void* g) {
    asm volatile("cp.async.ca.shared.global [%0], [%1], 16;" :: "r"(saddr), "l"(g));
}
#define CP_COMMIT() asm volatile("cp.async.commit_group;" ::: "memory")
#define CP_WAIT(n)  asm volatile("cp.async.wait_group %0;" :: "n"(n) : "memory")

// ---------------- 1) edge extraction -----------------------------------------
__global__ void k_extract(const float* __restrict__ adj) {
    __shared__ float srow[NN];
    __shared__ int   scnt[256];
    const int row = blockIdx.x, tid = threadIdx.x;
    const float4* arow4 = (const float4*)(adj + (size_t)row * NN);
    float4* srow4 = (float4*)srow;
    for (int j = tid; j < NN / 4; j += 256) srow4[j] = arow4[j];
    __syncthreads();

    int c = 0;
#pragma unroll
    for (int i = 0; i < 32; i++) if (srow[i * 256 + tid] > 0.f) c++;
    scnt[tid] = c;
    __syncthreads();
    for (int off = 1; off < 256; off <<= 1) {
        int v = scnt[tid];
        if (tid >= off) v += scnt[tid - off];
        __syncthreads();
        scnt[tid] = v;
        __syncthreads();
    }
    const int my_off = scnt[tid] - c;
    if (tid == 0) {
        int total = scnt[255];
        g_cnt[row] = total < CAP ? total : CAP;
    }
    const int base = row * CAP;
    int k = 0;
#pragma unroll
    for (int i = 0; i < 32; i++) {
        float v = srow[i * 256 + tid];
        if (v > 0.f) {
            int p = my_off + k;
            if (p < CAP) { g_ecol[base + p] = i * 256 + tid; g_eval[base + p] = v; }
            k++;
        }
    }
}

// ---------------- 2) fp32 -> bf16 hi/lo split (x) ----------------------------
__global__ void k_split(const float* __restrict__ s, __nv_bfloat16* __restrict__ h,
                        __nv_bfloat16* __restrict__ l, int n) {
    int i = blockIdx.x * 256 + threadIdx.x;
    if (i >= n) return;
    float v = s[i];
    __nv_bfloat16 hb = __float2bfloat16(v);
    h[i] = hb;
    l[i] = __float2bfloat16(v - __bfloat162float(hb));
}

// ---------------- 3) fused coalesced transpose+split of W1,W2,Wg -------------
// Wt[n*K + k] = W[k*N + n]; 32x32 smem tiles, 256 threads (32x8).
__global__ void k_wt3(const float* __restrict__ W1, const float* __restrict__ W2,
                      const float* __restrict__ Wg) {
    __shared__ float tile[32][33];
    int b = blockIdx.x;
    const float* W; __nv_bfloat16 *th, *tl; int K, N, tk, tn;
    if (b < 128) {        // W1: 512x256 -> 16x8 tiles
        W = W1; th = g_w1th; tl = g_w1tl; K = DIN; N = DHID;
        tk = (b >> 3) * 32; tn = (b & 7) * 32;
    } else if (b < 192) { // W2: 256x256 -> 8x8 tiles
        b -= 128; W = W2; th = g_w2th; tl = g_w2tl; K = DHID; N = DHID;
        tk = (b >> 3) * 32; tn = (b & 7) * 32;
    } else {              // Wg: 256x128 -> 8x4 tiles
        b -= 192; W = Wg; th = g_wgth; tl = g_wgtl; K = DHID; N = DOUT;
        tk = (b >> 2) * 32; tn = (b & 3) * 32;
    }
    const int tx = threadIdx.x & 31, ty = threadIdx.x >> 5;
#pragma unroll
    for (int i = 0; i < 32; i += 8)
        tile[ty + i][tx] = W[(size_t)(tk + ty + i) * N + tn + tx];
    __syncthreads();
#pragma unroll
    for (int i = 0; i < 32; i += 8) {
        float v = tile[tx][ty + i];
        __nv_bfloat16 hb = __float2bfloat16(v);
        size_t o = (size_t)(tn + ty + i) * K + tk + tx;
        th[o] = hb;
        tl[o] = __float2bfloat16(v - __bfloat162float(hb));
    }
}

// ---------------- 4) pipelined HMMA bf16-split GEMM --------------------------
// C[M,N] = (Ah+Al) @ (Bh+Bl)^T ; Bt stored [N][K] K-major.
// 512 thr, tile 128x128, warp 32x32, BK=32, 2-stage cp.async pipeline.
#define SPAD 40
#define ARR_B   (128 * SPAD * 2)          // 10240 B per (h/l x A/B) array
#define STAGE_B (4 * ARR_B)               // 40960 B per stage
#define OFF_AH  0
#define OFF_AL  ARR_B
#define OFF_BH  (2 * ARR_B)
#define OFF_BL  (3 * ARR_B)
__global__ void __launch_bounds__(512) k_hmma(
    const __nv_bfloat16* __restrict__ Ah, const __nv_bfloat16* __restrict__ Al,
    const __nv_bfloat16* __restrict__ Bh, const __nv_bfloat16* __restrict__ Bl,
    float* __restrict__ C, int N, int K)
{
    extern __shared__ char dsm[];
    const uint32_t sb = smem_to_u32(dsm);
    const int tid = threadIdx.x, wid = tid >> 5, lane = tid & 31;
    const int m0 = blockIdx.x * 128, n0 = blockIdx.y * 128;
    const int wm = (wid & 3) * 32, wn = (wid >> 2) * 32;

    float acc[2][4][4];
#pragma unroll
    for (int i = 0; i < 2; i++)
#pragma unroll
        for (int j = 0; j < 4; j++)
#pragma unroll
            for (int q = 0; q < 4; q++) acc[i][j][q] = 0.f;

    const int row = tid >> 2, ch = tid & 3;
    const uint32_t soffB = (uint32_t)(row * SPAD + ch * 8) * 2;

    const int nch = K >> 5;
    // stage issue
    {
        const size_t gA = (size_t)(m0 + row) * K + ch * 8;
        const size_t gB = (size_t)(n0 + row) * K + ch * 8;
        cp16(sb + OFF_AH + soffB, Ah + gA);
        cp16(sb + OFF_AL + soffB, Al + gA);
        cp16(sb + OFF_BH + soffB, Bh + gB);
        cp16(sb + OFF_BL + soffB, Bl + gB);
        CP_COMMIT();
    }

    for (int kc = 0; kc < nch; kc++) {
        if (kc + 1 < nch) {
            const uint32_t st = sb + ((kc + 1) & 1) * STAGE_B;
            const size_t gA = (size_t)(m0 + row) * K + (kc + 1) * 32 + ch * 8;
            const size_t gB = (size_t)(n0 + row) * K + (kc + 1) * 32 + ch * 8;
            cp16(st + OFF_AH + soffB, Ah + gA);
            cp16(st + OFF_AL + soffB, Al + gA);
            cp16(st + OFF_BH + soffB, Bh + gB);
            cp16(st + OFF_BL + soffB, Bl + gB);
            CP_COMMIT();
            CP_WAIT(1);
        } else {
            CP_WAIT(0);
        }
        __syncthreads();

        const uint32_t st = sb + (kc & 1) * STAGE_B;
#pragma unroll
        for (int ks = 0; ks < 2; ks++) {
            const int kb = ks * 16;
            const uint32_t aoff = ((wm + (lane & 15)) * SPAD + kb + 8 * (lane >> 4)) * 2;
            uint32_t afr[2][2][4];
            ldsm_x4(afr[0][0], st + OFF_AH + aoff);
            ldsm_x4(afr[0][1], st + OFF_AL + aoff);
            ldsm_x4(afr[1][0], st + OFF_AH + aoff + 16 * SPAD * 2);
            ldsm_x4(afr[1][1], st + OFF_AL + aoff + 16 * SPAD * 2);
            const uint32_t boff = ((wn + 8 * (lane >> 4) + (lane & 7)) * SPAD
                                   + kb + 8 * ((lane >> 3) & 1)) * 2;
            uint32_t bfr[2][2][4];
            ldsm_x4(bfr[0][0], st + OFF_BH + boff);
            ldsm_x4(bfr[0][1], st + OFF_BL + boff);
            ldsm_x4(bfr[1][0], st + OFF_BH + boff + 16 * SPAD * 2);
            ldsm_x4(bfr[1][1], st + OFF_BL + boff + 16 * SPAD * 2);

#pragma unroll
            for (int i = 0; i < 2; i++)
#pragma unroll
                for (int j = 0; j < 4; j++) {
                    const int p = j >> 1, s = (j & 1) * 2;
                    mma16816(acc[i][j], afr[i][0], bfr[p][0][s], bfr[p][0][s + 1]);
                    mma16816(acc[i][j], afr[i][0], bfr[p][1][s], bfr[p][1][s + 1]);
                    mma16816(acc[i][j], afr[i][1], bfr[p][0][s], bfr[p][0][s + 1]);
                }
        }
        __syncthreads();
    }

    const int g = lane >> 2, t2 = (lane & 3) * 2;
#pragma unroll
    for (int i = 0; i < 2; i++)
#pragma unroll
        for (int j = 0; j < 4; j++) {
            const int rm = m0 + wm + 16 * i + g;
            const int cn = n0 + wn + 8 * j + t2;
            *(float2*)&C[(size_t)rm * N + cn]       = make_float2(acc[i][j][0], acc[i][j][1]);
            *(float2*)&C[(size_t)(rm + 8) * N + cn] = make_float2(acc[i][j][2], acc[i][j][3]);
        }
}

// ---------------- 5) sparse SpMM (4 rows/block) + bias + leaky -> bf16 h/l ----
__global__ void k_spmm(const float* __restrict__ y, const float* __restrict__ bias,
                       __nv_bfloat16* __restrict__ oh, __nv_bfloat16* __restrict__ ol) {
    __shared__ int   scol[4][CAP];
    __shared__ float sval[4][CAP];
    const int r0 = blockIdx.x * 4, tid = threadIdx.x;  // 256 threads
    int cnt[4];
#pragma unroll
    for (int rr = 0; rr < 4; rr++) {
        cnt[rr] = g_cnt[r0 + rr];
        for (int t = tid; t < cnt[rr]; t += 256) {
            scol[rr][t] = g_ecol[(r0 + rr) * CAP + t];
            sval[rr][t] = g_eval[(r0 + rr) * CAP + t];
        }
    }
    __syncthreads();
    int cmax = max(max(cnt[0], cnt[1]), max(cnt[2], cnt[3]));
    float acc[4] = {0.f, 0.f, 0.f, 0.f};
    for (int t = 0; t < cmax; t++) {
#pragma unroll
        for (int rr = 0; rr < 4; rr++)
            if (t < cnt[rr])
                acc[rr] = fmaf(sval[rr][t], y[(size_t)scol[rr][t] * DHID + tid], acc[rr]);
    }
    const float bv = bias[tid];
#pragma unroll
    for (int rr = 0; rr < 4; rr++) {
        float v = leaky(acc[rr] + bv);
        __nv_bfloat16 hb = __float2bfloat16(v);
        size_t idx = (size_t)(r0 + rr) * DHID + tid;
        oh[idx] = hb;
        ol[idx] = __float2bfloat16(v - __bfloat162float(hb));
    }
}

// ---------------- 6) f1 = h@a1, f2 = h@a2 ------------------------------------
__global__ void k_f12(const float* __restrict__ h, const float* __restrict__ a) {
    const int warp = (blockIdx.x * blockDim.x + threadIdx.x) >> 5;
    const int lane = threadIdx.x & 31;
    if (warp >= NN) return;
    const float* hr = h + (size_t)warp * DOUT;
    float s1 = 0.f, s2 = 0.f;
#pragma unroll
    for (int q = 0; q < 4; q++) {
        int c = lane + q * 32;
        float hv = hr[c];
        s1 = fmaf(hv, a[c], s1);
        s2 = fmaf(hv, a[DOUT + c], s2);
    }
#pragma unroll
    for (int o = 16; o; o >>= 1) {
        s1 += __shfl_down_sync(0xffffffffu, s1, o);
        s2 += __shfl_down_sync(0xffffffffu, s2, o);
    }
    if (lane == 0) { g_f1[warp] = s1; g_f2[warp] = s2; }
}

// ---------------- 7) column mean of h ----------------------------------------
__global__ void k_part(const float* __restrict__ h) {
    const int b = blockIdx.x, c = threadIdx.x;
    float s = 0.f;
    for (int r = 0; r < 128; r++) s += h[(size_t)(b * 128 + r) * DOUT + c];
    g_part[b * DOUT + c] = s;
}
__global__ void k_mean() {
    const int c = threadIdx.x;
    float s = 0.f;
    for (int b = 0; b < 64; b++) s += g_part[b * DOUT + c];
    g_hmean[c] = s * (1.f / NN);
}

// ---------------- 8) sparse masked softmax + h_prime + leaky + split ----------
__global__ void k_attn(const float* __restrict__ h, float* __restrict__ out) {
    __shared__ float se[CAP];
    __shared__ int   scol[CAP];
    __shared__ float sred[128];
    const int row = blockIdx.x, tid = threadIdx.x;   // 128 threads
    const int cnt = g_cnt[row];

    if (cnt == 0) {
        float v = leaky(g_hmean[tid]);
        if (tid < 64) out[(size_t)row * 64 + tid] = v;
        else          out[(size_t)NN * 64 + (size_t)row * 64 + (tid - 64)] = v;
        return;
    }

    const float f1i = g_f1[row];
    float lmax = -INFINITY;
    for (int t = tid; t < cnt; t += 128) {
        int j = g_ecol[row * CAP + t];
        float e = leaky(f1i + g_f2[j]);
        scol[t] = j;
        se[t] = e;
        lmax = fmaxf(lmax, e);
    }
    sred[tid] = lmax;
    __syncthreads();
    for (int s = 64; s; s >>= 1) {
        if (tid < s) sred[tid] = fmaxf(sred[tid], sred[tid + s]);
        __syncthreads();
    }
    const float m = sred[0];
    __syncthreads();

    float lsum = 0.f;
    for (int t = tid; t < cnt; t += 128) {
        float w = __expf(se[t] - m);
        se[t] = w;
        lsum += w;
    }
    sred[tid] = lsum;
    __syncthreads();
    for (int s = 64; s; s >>= 1) {
        if (tid < s) sred[tid] += sred[tid + s];
        __syncthreads();
    }
    const float invZ = 1.f / sred[0];

    float a0 = 0.f, a1 = 0.f, a2 = 0.f, a3 = 0.f;
    int t = 0;
    for (; t + 4 <= cnt; t += 4) {
        a0 = fmaf(se[t],     h[(size_t)scol[t]     * DOUT + tid], a0);
        a1 = fmaf(se[t + 1], h[(size_t)scol[t + 1] * DOUT + tid], a1);
        a2 = fmaf(se[t + 2], h[(size_t)scol[t + 2] * DOUT + tid], a2);
        a3 = fmaf(se[t + 3], h[(size_t)scol[t + 3] * DOUT + tid], a3);
    }
    for (; t < cnt; t++)
        a0 = fmaf(se[t], h[(size_t)scol[t] * DOUT + tid], a0);
    float v = leaky(((a0 + a1) + (a2 + a3)) * invZ);
    if (tid < 64) out[(size_t)row * 64 + tid] = v;
    else          out[(size_t)NN * 64 + (size_t)row * 64 + (tid - 64)] = v;
}

// ---------------- launch -----------------------------------------------------
extern "C" void kernel_launch(void* const* d_in, const int* in_sizes, int n_in,
                              void* d_out, int out_size) {
    (void)in_sizes; (void)n_in; (void)out_size;
    const float* x   = (const float*)d_in[0];
    const float* adj = (const float*)d_in[1];
    const float* W1  = (const float*)d_in[2];
    const float* b1  = (const float*)d_in[3];
    const float* W2  = (const float*)d_in[4];
    const float* b2  = (const float*)d_in[5];
    const float* Wg  = (const float*)d_in[6];
    const float* a   = (const float*)d_in[7];
    float* out = (float*)d_out;

    void* p;
    cudaGetSymbolAddress(&p, g_y1);   float* y1 = (float*)p;
    cudaGetSymbolAddress(&p, g_y2);   float* y2 = (float*)p;
    cudaGetSymbolAddress(&p, g_h);    float* h  = (float*)p;
    cudaGetSymbolAddress(&p, g_xh);   __nv_bfloat16* xh  = (__nv_bfloat16*)p;
    cudaGetSymbolAddress(&p, g_xl);   __nv_bfloat16* xl  = (__nv_bfloat16*)p;
    cudaGetSymbolAddress(&p, g_x1h);  __nv_bfloat16* x1h = (__nv_bfloat16*)p;
    cudaGetSymbolAddress(&p, g_x1l);  __nv_bfloat16* x1l = (__nv_bfloat16*)p;
    cudaGetSymbolAddress(&p, g_x2h);  __nv_bfloat16* x2h = (__nv_bfloat16*)p;
    cudaGetSymbolAddress(&p, g_x2l);  __nv_bfloat16* x2l = (__nv_bfloat16*)p;
    cudaGetSymbolAddress(&p, g_w1th); __nv_bfloat16* w1th = (__nv_bfloat16*)p;
    cudaGetSymbolAddress(&p, g_w1tl); __nv_bfloat16* w1tl = (__nv_bfloat16*)p;
    cudaGetSymbolAddress(&p, g_w2th); __nv_bfloat16* w2th = (__nv_bfloat16*)p;
    cudaGetSymbolAddress(&p, g_w2tl); __nv_bfloat16* w2tl = (__nv_bfloat16*)p;
    cudaGetSymbolAddress(&p, g_wgth); __nv_bfloat16* wgth = (__nv_bfloat16*)p;
    cudaGetSymbolAddress(&p, g_wgtl); __nv_bfloat16* wgtl = (__nv_bfloat16*)p;

    cudaFuncSetAttribute(k_hmma, cudaFuncAttributeMaxDynamicSharedMemorySize, 2 * STAGE_B);

    // launch order puts hmma GEMM1 in the profiled (4th) slot
    k_extract<<<NN, 256>>>(adj);                               // 1
    k_split<<<(NN * DIN + 255) / 256, 256>>>(x, xh, xl, NN * DIN); // 2
    k_wt3<<<224, 256>>>(W1, W2, Wg);                           // 3

    k_hmma<<<dim3(NN / 128, DHID / 128), 512, 2 * STAGE_B>>>(xh,  xl,  w1th, w1tl, y1, DHID, DIN);  // 4
    k_spmm<<<NN / 4, 256>>>(y1, b1, x1h, x1l);                 // 5
    k_hmma<<<dim3(NN / 128, DHID / 128), 512, 2 * STAGE_B>>>(x1h, x1l, w2th, w2tl, y2, DHID, DHID); // 6
    k_spmm<<<NN / 4, 256>>>(y2, b2, x2h, x2l);                 // 7
    k_hmma<<<dim3(NN / 128, DOUT / 128), 512, 2 * STAGE_B>>>(x2h, x2l, wgth, wgtl, h,  DOUT, DHID); // 8

    k_f12 <<<NN / 8, 256>>>(h, a);                             // 9
    k_part<<<64, 128>>>(h);                                    // 10
    k_mean<<<1, 128>>>();                                      // 11
    k_attn<<<NN, 128>>>(h, out);                               // 12
}

// round 7
// speedup vs baseline: 1.4307x; 1.0525x over previous
#include <cuda_runtime.h>
#include <cuda_bf16.h>
#include <math.h>
#include <stdint.h>

#define NN   8192
#define DIN  512
#define DHID 256
#define DOUT 128
#define CAP  256
#define NEG  0.25f

// ---------------- scratch (device globals) ----------------------------------
__device__ float g_y1[NN * DHID];
__device__ float g_y2[NN * DHID];
__device__ float g_h [NN * DOUT];
__device__ float g_f1[NN];
__device__ float g_f2[NN];
__device__ int   g_cnt [NN];
__device__ int   g_ecol[NN * CAP];
__device__ float g_eval[NN * CAP];
__device__ float g_part[64 * DOUT];
__device__ float g_hmean[DOUT];

__device__ __nv_bfloat16 g_xh [NN * DIN],  g_xl [NN * DIN];
__device__ __nv_bfloat16 g_x1h[NN * DHID], g_x1l[NN * DHID];
__device__ __nv_bfloat16 g_x2h[NN * DHID], g_x2l[NN * DHID];
__device__ __nv_bfloat16 g_w1th[DHID * DIN],  g_w1tl[DHID * DIN];
__device__ __nv_bfloat16 g_w2th[DHID * DHID], g_w2tl[DHID * DHID];
__device__ __nv_bfloat16 g_wgth[DOUT * DHID], g_wgtl[DOUT * DHID];

__device__ __forceinline__ float leaky(float x) { return x >= 0.f ? x : NEG * x; }

__device__ __forceinline__ uint32_t smem_to_u32(const void* p) {
    uint32_t a;
    asm("{ .reg .u64 t; cvta.to.shared.u64 t, %1; cvt.u32.u64 %0, t; }" : "=r"(a) : "l"(p));
    return a;
}
__device__ __forceinline__ void ldsm_x4(uint32_t* r, uint32_t addr) {
    asm volatile("ldmatrix.sync.aligned.m8n8.x4.shared.b16 {%0,%1,%2,%3}, [%4];"
                 : "=r"(r[0]), "=r"(r[1]), "=r"(r[2]), "=r"(r[3]) : "r"(addr));
}
__device__ __forceinline__ void mma16816(float* c, const uint32_t* a, uint32_t b0, uint32_t b1) {
    asm volatile("mma.sync.aligned.m16n8k16.row.col.f32.bf16.bf16.f32 "
                 "{%0,%1,%2,%3}, {%4,%5,%6,%7}, {%8,%9}, {%0,%1,%2,%3};"
                 : "+f"(c[0]), "+f"(c[1]), "+f"(c[2]), "+f"(c[3])
                 : "r"(a[0]), "r"(a[1]), "r"(a[2]), "r"(a[3]), "r"(b0), "r"(b1));
}
__device__ __forceinline__ void cp16(uint32_t saddr, const void* g) {
    asm volatile("cp.async.ca.shared.global [%0], [%1], 16;" :: "r"(saddr), "l"(g));
}
#define CP_COMMIT() asm volatile("cp.async.commit_group;" ::: "memory")
#define CP_WAIT(n)  asm volatile("cp.async.wait_group %0;" :: "n"(n) : "memory")

// ---------------- 1) edge extraction -----------------------------------------
__global__ void k_extract(const float* __restrict__ adj) {
    __shared__ float srow[NN];
    __shared__ int   scnt[256];
    const int row = blockIdx.x, tid = threadIdx.x;
    const float4* arow4 = (const float4*)(adj + (size_t)row * NN);
    float4* srow4 = (float4*)srow;
    for (int j = tid; j < NN / 4; j += 256) srow4[j] = arow4[j];
    __syncthreads();

    int c = 0;
#pragma unroll
    for (int i = 0; i < 32; i++) if (srow[i * 256 + tid] > 0.f) c++;
    scnt[tid] = c;
    __syncthreads();
    for (int off = 1; off < 256; off <<= 1) {
        int v = scnt[tid];
        if (tid >= off) v += scnt[tid - off];
        __syncthreads();
        scnt[tid] = v;
        __syncthreads();
    }
    const int my_off = scnt[tid] - c;
    if (tid == 0) {
        int total = scnt[255];
        g_cnt[row] = total < CAP ? total : CAP;
    }
    const int base = row * CAP;
    int k = 0;
#pragma unroll
    for (int i = 0; i < 32; i++) {
        float v = srow[i * 256 + tid];
        if (v > 0.f) {
            int p = my_off + k;
            if (p < CAP) { g_ecol[base + p] = i * 256 + tid; g_eval[base + p] = v; }
            k++;
        }
    }
}

// ---------------- 2) fp32 -> bf16 hi/lo split (x), vectorized ----------------
__global__ void k_split(const float* __restrict__ s, __nv_bfloat16* __restrict__ h,
                        __nv_bfloat16* __restrict__ l, int n4) {
    int i = blockIdx.x * 256 + threadIdx.x;
    if (i >= n4) return;
    float4 v = ((const float4*)s)[i];
    __nv_bfloat16 h0 = __float2bfloat16(v.x), h1 = __float2bfloat16(v.y);
    __nv_bfloat16 h2 = __float2bfloat16(v.z), h3 = __float2bfloat16(v.w);
    __nv_bfloat162* hp = (__nv_bfloat162*)h;
    __nv_bfloat162* lp = (__nv_bfloat162*)l;
    hp[2 * i]     = __nv_bfloat162(h0, h1);
    hp[2 * i + 1] = __nv_bfloat162(h2, h3);
    lp[2 * i]     = __nv_bfloat162(__float2bfloat16(v.x - __bfloat162float(h0)),
                                   __float2bfloat16(v.y - __bfloat162float(h1)));
    lp[2 * i + 1] = __nv_bfloat162(__float2bfloat16(v.z - __bfloat162float(h2)),
                                   __float2bfloat16(v.w - __bfloat162float(h3)));
}

// ---------------- 3) fused coalesced transpose+split of W1,W2,Wg -------------
__global__ void k_wt3(const float* __restrict__ W1, const float* __restrict__ W2,
                      const float* __restrict__ Wg) {
    __shared__ float tile[32][33];
    int b = blockIdx.x;
    const float* W; __nv_bfloat16 *th, *tl; int K, N, tk, tn;
    if (b < 128) {
        W = W1; th = g_w1th; tl = g_w1tl; K = DIN; N = DHID;
        tk = (b >> 3) * 32; tn = (b & 7) * 32;
    } else if (b < 192) {
        b -= 128; W = W2; th = g_w2th; tl = g_w2tl; K = DHID; N = DHID;
        tk = (b >> 3) * 32; tn = (b & 7) * 32;
    } else {
        b -= 192; W = Wg; th = g_wgth; tl = g_wgtl; K = DHID; N = DOUT;
        tk = (b >> 2) * 32; tn = (b & 3) * 32;
    }
    const int tx = threadIdx.x & 31, ty = threadIdx.x >> 5;
#pragma unroll
    for (int i = 0; i < 32; i += 8)
        tile[ty + i][tx] = W[(size_t)(tk + ty + i) * N + tn + tx];
    __syncthreads();
#pragma unroll
    for (int i = 0; i < 32; i += 8) {
        float v = tile[tx][ty + i];
        __nv_bfloat16 hb = __float2bfloat16(v);
        size_t o = (size_t)(tn + ty + i) * K + tk + tx;
        th[o] = hb;
        tl[o] = __float2bfloat16(v - __bfloat162float(hb));
    }
}

// ---------------- 4) 3-stage pipelined HMMA bf16-split GEMM ------------------
// C[M,N] = (Ah+Al)(Bh+Bl)^T ; Bt [N][K] K-major. Warp tile 32x32, BK=32.
#define SPAD 40
template<int BM, int BN, int WM, int WN>
__global__ void __launch_bounds__(WM * WN * 32) k_hmma(
    const __nv_bfloat16* __restrict__ Ah, const __nv_bfloat16* __restrict__ Al,
    const __nv_bfloat16* __restrict__ Bh, const __nv_bfloat16* __restrict__ Bl,
    float* __restrict__ C, int N, int K)
{
    constexpr int T = WM * WN * 32;
    constexpr int ARR_A = BM * SPAD * 2;       // bytes per A array
    constexpr int ARR_BB = BN * SPAD * 2;      // bytes per B array
    constexpr int OFF_AH = 0;
    constexpr int OFF_AL = ARR_A;
    constexpr int OFF_BH = 2 * ARR_A;
    constexpr int OFF_BL = 2 * ARR_A + ARR_BB;
    constexpr int STAGE  = 2 * ARR_A + 2 * ARR_BB;

    extern __shared__ char dsm[];
    const uint32_t sb = smem_to_u32(dsm);
    const int tid = threadIdx.x, wid = tid >> 5, lane = tid & 31;
    const int m0 = blockIdx.x * BM, n0 = blockIdx.y * BN;
    const int wm = (wid % WM) * 32, wn = (wid / WM) * 32;

    float acc[2][4][4];
#pragma unroll
    for (int i = 0; i < 2; i++)
#pragma unroll
        for (int j = 0; j < 4; j++)
#pragma unroll
            for (int q = 0; q < 4; q++) acc[i][j][q] = 0.f;

    const int nch = K >> 5;

    auto issue = [&](int kc) {
        const uint32_t st = sb + (kc % 3) * STAGE;
#pragma unroll
        for (int idx = tid; idx < BM * 4; idx += T) {
            const int r = idx >> 2, c = idx & 3;
            const uint32_t so = (uint32_t)(r * SPAD + c * 8) * 2;
            const size_t gA = (size_t)(m0 + r) * K + kc * 32 + c * 8;
            cp16(st + OFF_AH + so, Ah + gA);
            cp16(st + OFF_AL + so, Al + gA);
        }
#pragma unroll
        for (int idx = tid; idx < BN * 4; idx += T) {
            const int r = idx >> 2, c = idx & 3;
            const uint32_t so = (uint32_t)(r * SPAD + c * 8) * 2;
            const size_t gB = (size_t)(n0 + r) * K + kc * 32 + c * 8;
            cp16(st + OFF_BH + so, Bh + gB);
            cp16(st + OFF_BL + so, Bl + gB);
        }
        CP_COMMIT();
    };

    issue(0);
    issue(1);

    for (int kc = 0; kc < nch; kc++) {
        if (kc + 1 < nch) { CP_WAIT(1); } else { CP_WAIT(0); }
        __syncthreads();
        if (kc + 2 < nch) issue(kc + 2);

        const uint32_t st = sb + (kc % 3) * STAGE;
#pragma unroll
        for (int ks = 0; ks < 2; ks++) {
            const int kb = ks * 16;
            const uint32_t aoff = ((wm + (lane & 15)) * SPAD + kb + 8 * (lane >> 4)) * 2;
            uint32_t afr[2][2][4];
            ldsm_x4(afr[0][0], st + OFF_AH + aoff);
            ldsm_x4(afr[0][1], st + OFF_AL + aoff);
            ldsm_x4(afr[1][0], st + OFF_AH + aoff + 16 * SPAD * 2);
            ldsm_x4(afr[1][1], st + OFF_AL + aoff + 16 * SPAD * 2);
            const uint32_t boff = ((wn + 8 * (lane >> 4) + (lane & 7)) * SPAD
                                   + kb + 8 * ((lane >> 3) & 1)) * 2;
            uint32_t bfr[2][2][4];
            ldsm_x4(bfr[0][0], st + OFF_BH + boff);
            ldsm_x4(bfr[0][1], st + OFF_BL + boff);
            ldsm_x4(bfr[1][0], st + OFF_BH + boff + 16 * SPAD * 2);
            ldsm_x4(bfr[1][1], st + OFF_BL + boff + 16 * SPAD * 2);

#pragma unroll
            for (int i = 0; i < 2; i++)
#pragma unroll
                for (int j = 0; j < 4; j++) {
                    const int p = j >> 1, s = (j & 1) * 2;
                    mma16816(acc[i][j], afr[i][0], bfr[p][0][s], bfr[p][0][s + 1]);
                    mma16816(acc[i][j], afr[i][0], bfr[p][1][s], bfr[p][1][s + 1]);
                    mma16816(acc[i][j], afr[i][1], bfr[p][0][s], bfr[p][0][s + 1]);
                }
        }
    }

    const int g = lane >> 2, t2 = (lane & 3) * 2;
#pragma unroll
    for (int i = 0; i < 2; i++)
#pragma unroll
        for (int j = 0; j < 4; j++) {
            const int rm = m0 + wm + 16 * i + g;
            const int cn = n0 + wn + 8 * j + t2;
            *(float2*)&C[(size_t)rm * N + cn]       = make_float2(acc[i][j][0], acc[i][j][1]);
            *(float2*)&C[(size_t)(rm + 8) * N + cn] = make_float2(acc[i][j][2], acc[i][j][3]);
        }
}

// ---------------- 5) sparse SpMM (4 rows/block) + bias + leaky -> bf16 h/l ----
__global__ void k_spmm(const float* __restrict__ y, const float* __restrict__ bias,
                       __nv_bfloat16* __restrict__ oh, __nv_bfloat16* __restrict__ ol) {
    __shared__ int   scol[4][CAP];
    __shared__ float sval[4][CAP];
    const int r0 = blockIdx.x * 4, tid = threadIdx.x;
    int cnt[4];
#pragma unroll
    for (int rr = 0; rr < 4; rr++) {
        cnt[rr] = g_cnt[r0 + rr];
        for (int t = tid; t < cnt[rr]; t += 256) {
            scol[rr][t] = g_ecol[(r0 + rr) * CAP + t];
            sval[rr][t] = g_eval[(r0 + rr) * CAP + t];
        }
    }
    __syncthreads();
    int cmax = max(max(cnt[0], cnt[1]), max(cnt[2], cnt[3]));
    float acc[4] = {0.f, 0.f, 0.f, 0.f};
    for (int t = 0; t < cmax; t++) {
#pragma unroll
        for (int rr = 0; rr < 4; rr++)
            if (t < cnt[rr])
                acc[rr] = fmaf(sval[rr][t], y[(size_t)scol[rr][t] * DHID + tid], acc[rr]);
    }
    const float bv = bias[tid];
#pragma unroll
    for (int rr = 0; rr < 4; rr++) {
        float v = leaky(acc[rr] + bv);
        __nv_bfloat16 hb = __float2bfloat16(v);
        size_t idx = (size_t)(r0 + rr) * DHID + tid;
        oh[idx] = hb;
        ol[idx] = __float2bfloat16(v - __bfloat162float(hb));
    }
}

// ---------------- 6) f1 = h@a1, f2 = h@a2 ------------------------------------
__global__ void k_f12(const float* __restrict__ h, const float* __restrict__ a) {
    const int warp = (blockIdx.x * blockDim.x + threadIdx.x) >> 5;
    const int lane = threadIdx.x & 31;
    if (warp >= NN) return;
    const float* hr = h + (size_t)warp * DOUT;
    float s1 = 0.f, s2 = 0.f;
#pragma unroll
    for (int q = 0; q < 4; q++) {
        int c = lane + q * 32;
        float hv = hr[c];
        s1 = fmaf(hv, a[c], s1);
        s2 = fmaf(hv, a[DOUT + c], s2);
    }
#pragma unroll
    for (int o = 16; o; o >>= 1) {
        s1 += __shfl_down_sync(0xffffffffu, s1, o);
        s2 += __shfl_down_sync(0xffffffffu, s2, o);
    }
    if (lane == 0) { g_f1[warp] = s1; g_f2[warp] = s2; }
}

// ---------------- 7) column mean of h ----------------------------------------
__global__ void k_part(const float* __restrict__ h) {
    const int b = blockIdx.x, c = threadIdx.x;
    float s = 0.f;
    for (int r = 0; r < 128; r++) s += h[(size_t)(b * 128 + r) * DOUT + c];
    g_part[b * DOUT + c] = s;
}
__global__ void k_mean() {
    const int c = threadIdx.x;
    float s = 0.f;
    for (int b = 0; b < 64; b++) s += g_part[b * DOUT + c];
    g_hmean[c] = s * (1.f / NN);
}

// ---------------- 8) sparse masked softmax + h_prime + leaky + split ----------
__global__ void k_attn(const float* __restrict__ h, float* __restrict__ out) {
    __shared__ float se[CAP];
    __shared__ int   scol[CAP];
    __shared__ float sred[128];
    const int row = blockIdx.x, tid = threadIdx.x;
    const int cnt = g_cnt[row];

    if (cnt == 0) {
        float v = leaky(g_hmean[tid]);
        if (tid < 64) out[(size_t)row * 64 + tid] = v;
        else          out[(size_t)NN * 64 + (size_t)row * 64 + (tid - 64)] = v;
        return;
    }

    const float f1i = g_f1[row];
    float lmax = -INFINITY;
    for (int t = tid; t < cnt; t += 128) {
        int j = g_ecol[row * CAP + t];
        float e = leaky(f1i + g_f2[j]);
        scol[t] = j;
        se[t] = e;
        lmax = fmaxf(lmax, e);
    }
    sred[tid] = lmax;
    __syncthreads();
    for (int s = 64; s; s >>= 1) {
        if (tid < s) sred[tid] = fmaxf(sred[tid], sred[tid + s]);
        __syncthreads();
    }
    const float m = sred[0];
    __syncthreads();

    float lsum = 0.f;
    for (int t = tid; t < cnt; t += 128) {
        float w = __expf(se[t] - m);
        se[t] = w;
        lsum += w;
    }
    sred[tid] = lsum;
    __syncthreads();
    for (int s = 64; s; s >>= 1) {
        if (tid < s) sred[tid] += sred[tid + s];
        __syncthreads();
    }
    const float invZ = 1.f / sred[0];

    float a0 = 0.f, a1 = 0.f, a2 = 0.f, a3 = 0.f;
    int t = 0;
    for (; t + 4 <= cnt; t += 4) {
        a0 = fmaf(se[t],     h[(size_t)scol[t]     * DOUT + tid], a0);
        a1 = fmaf(se[t + 1], h[(size_t)scol[t + 1] * DOUT + tid], a1);
        a2 = fmaf(se[t + 2], h[(size_t)scol[t + 2] * DOUT + tid], a2);
        a3 = fmaf(se[t + 3], h[(size_t)scol[t + 3] * DOUT + tid], a3);
    }
    for (; t < cnt; t++)
        a0 = fmaf(se[t], h[(size_t)scol[t] * DOUT + tid], a0);
    float v = leaky(((a0 + a1) + (a2 + a3)) * invZ);
    if (tid < 64) out[(size_t)row * 64 + tid] = v;
    else          out[(size_t)NN * 64 + (size_t)row * 64 + (tid - 64)] = v;
}

// ---------------- launch -----------------------------------------------------
extern "C" void kernel_launch(void* const* d_in, const int* in_sizes, int n_in,
                              void* d_out, int out_size) {
    (void)in_sizes; (void)n_in; (void)out_size;
    const float* x   = (const float*)d_in[0];
    const float* adj = (const float*)d_in[1];
    const float* W1  = (const float*)d_in[2];
    const float* b1  = (const float*)d_in[3];
    const float* W2  = (const float*)d_in[4];
    const float* b2  = (const float*)d_in[5];
    const float* Wg  = (const float*)d_in[6];
    const float* a   = (const float*)d_in[7];
    float* out = (float*)d_out;

    void* p;
    cudaGetSymbolAddress(&p, g_y1);   float* y1 = (float*)p;
    cudaGetSymbolAddress(&p, g_y2);   float* y2 = (float*)p;
    cudaGetSymbolAddress(&p, g_h);    float* h  = (float*)p;
    cudaGetSymbolAddress(&p, g_xh);   __nv_bfloat16* xh  = (__nv_bfloat16*)p;
    cudaGetSymbolAddress(&p, g_xl);   __nv_bfloat16* xl  = (__nv_bfloat16*)p;
    cudaGetSymbolAddress(&p, g_x1h);  __nv_bfloat16* x1h = (__nv_bfloat16*)p;
    cudaGetSymbolAddress(&p, g_x1l);  __nv_bfloat16* x1l = (__nv_bfloat16*)p;
    cudaGetSymbolAddress(&p, g_x2h);  __nv_bfloat16* x2h = (__nv_bfloat16*)p;
    cudaGetSymbolAddress(&p, g_x2l);  __nv_bfloat16* x2l = (__nv_bfloat16*)p;
    cudaGetSymbolAddress(&p, g_w1th); __nv_bfloat16* w1th = (__nv_bfloat16*)p;
    cudaGetSymbolAddress(&p, g_w1tl); __nv_bfloat16* w1tl = (__nv_bfloat16*)p;
    cudaGetSymbolAddress(&p, g_w2th); __nv_bfloat16* w2th = (__nv_bfloat16*)p;
    cudaGetSymbolAddress(&p, g_w2tl); __nv_bfloat16* w2tl = (__nv_bfloat16*)p;
    cudaGetSymbolAddress(&p, g_wgth); __nv_bfloat16* wgth = (__nv_bfloat16*)p;
    cudaGetSymbolAddress(&p, g_wgtl); __nv_bfloat16* wgtl = (__nv_bfloat16*)p;

    constexpr int SMEM_BIG   = 3 * (2 * 128 * SPAD * 2 + 2 * 128 * SPAD * 2); // 122880
    constexpr int SMEM_SMALL = 3 * (2 * 64 * SPAD * 2 + 2 * 128 * SPAD * 2);  // 92160
    cudaFuncSetAttribute(k_hmma<128, 128, 4, 4>, cudaFuncAttributeMaxDynamicSharedMemorySize, SMEM_BIG);
    cudaFuncSetAttribute(k_hmma<64, 128, 2, 4>,  cudaFuncAttributeMaxDynamicSharedMemorySize, SMEM_SMALL);

    k_extract<<<NN, 256>>>(adj);                                   // 1
    k_split<<<(NN * DIN / 4 + 255) / 256, 256>>>(x, xh, xl, NN * DIN / 4); // 2
    k_wt3<<<224, 256>>>(W1, W2, Wg);                               // 3

    k_hmma<128, 128, 4, 4><<<dim3(NN / 128, DHID / 128), 512, SMEM_BIG>>>(
        xh, xl, w1th, w1tl, y1, DHID, DIN);                        // 4 (profiled slot)
    k_spmm<<<NN / 4, 256>>>(y1, b1, x1h, x1l);                     // 5
    k_hmma<128, 128, 4, 4><<<dim3(NN / 128, DHID / 128), 512, SMEM_BIG>>>(
        x1h, x1l, w2th, w2tl, y2, DHID, DHID);                     // 6
    k_spmm<<<NN / 4, 256>>>(y2, b2, x2h, x2l);                     // 7
    k_hmma<64, 128, 2, 4><<<dim3(NN / 64, DOUT / 128), 256, SMEM_SMALL>>>(
        x2h, x2l, wgth, wgtl, h, DOUT, DHID);                      // 8

    k_f12 <<<NN / 8, 256>>>(h, a);                                 // 9
    k_part<<<64, 128>>>(h);                                        // 10
    k_mean<<<1, 128>>>();                                          // 11
    k_attn<<<NN, 128>>>(h, out);                                   // 12
}